// round 9
// baseline (speedup 1.0000x reference)
#include <cuda_runtime.h>

// AbstractionLayer: B=524288, I=12, R=6, J=2, L=2, V=4
// Packed f32x2, 2 elements/thread (t, t+B/2). Features register-resident
// (24 packed u64 = 48 regs), zero inner-loop shared memory; one (r,j) per
// sweep (12 sweeps). R9: reg diet (output pointers recomputed at store via
// a uniform offset instead of held live through the loop) + launch_bounds
// (128,7) -> 72-reg cap, 7 blocks/SM, occ 32 -> ~38%.
// Softmax max-pass removed (logits bounded); log2e folded into coefs (raw
// ex2.approx); head*body pre-fused; rcp.approx (tol 1e-3).

#define NI 12
#define NR 6
#define NJ 2
#define NL 2
#define NV 4
#define NRJ 12
#define NT 128
#define LOG2E 1.4426950408889634f

typedef unsigned long long u64;

__device__ __forceinline__ u64 pk2(float lo, float hi) {
    u64 r; asm("mov.b64 %0, {%1,%2};" : "=l"(r) : "f"(lo), "f"(hi)); return r;
}
__device__ __forceinline__ void upk2(u64 v, float& lo, float& hi) {
    asm("mov.b64 {%0,%1}, %2;" : "=f"(lo), "=f"(hi) : "l"(v));
}
__device__ __forceinline__ u64 fma2(u64 a, u64 b, u64 c) {
    u64 d; asm("fma.rn.f32x2 %0, %1, %2, %3;" : "=l"(d) : "l"(a), "l"(b), "l"(c)); return d;
}
__device__ __forceinline__ u64 mul2(u64 a, u64 b) {
    u64 d; asm("mul.rn.f32x2 %0, %1, %2;" : "=l"(d) : "l"(a), "l"(b)); return d;
}
__device__ __forceinline__ u64 add2(u64 a, u64 b) {
    u64 d; asm("add.rn.f32x2 %0, %1, %2;" : "=l"(d) : "l"(a), "l"(b)); return d;
}
__device__ __forceinline__ float ex2a(float x) {
    float r; asm("ex2.approx.ftz.f32 %0, %1;" : "=f"(r) : "f"(x)); return r;
}
__device__ __forceinline__ float rcpa(float x) {
    float r; asm("rcp.approx.ftz.f32 %0, %1;" : "=f"(r) : "f"(x)); return r;
}

__global__ __launch_bounds__(NT, 7)
void abstraction_layer_kernel(
    const float* __restrict__ feat,       // [B, I, L]
    const float* __restrict__ templates,  // [R, J, L]
    const float* __restrict__ gammas,     // [R, J, L]
    const float* __restrict__ body_W,     // [R, J, V, L]
    const float* __restrict__ body_b,     // [R, J, V]
    const float* __restrict__ head_W,     // [R, L, V]
    const float* __restrict__ head_b,     // [R, L]
    float* __restrict__ out,              // [B, R, L]
    int B)
{
    __shared__ u64 s_coef[NRJ][4];       // log2e-scaled logit coefs, lane-dup
    __shared__ u64 s_M[NRJ][4];          // fused head*body, lane-dup
    __shared__ u64 s_c[NR * NL];         // fused bias, lane-dup

    const int tid = threadIdx.x;

    // ---- one-time parameter fusion (disjoint thread ranges) ----
    if (tid < NRJ) {
        const int r = tid >> 1, j = tid & 1;
        #pragma unroll
        for (int l = 0; l < NL; l++) {
            float g = gammas[(r * NJ + j) * NL + l];
            g = fminf(fmaxf(g, 0.0f), 1.0f);
            const float w = 1.0f - g;
            const float t = templates[(r * NJ + j) * NL + l];
            const float clin  = 2.0f * w * t * LOG2E;
            const float cquad = -w * LOG2E;
            s_coef[tid][l]     = pk2(clin, clin);
            s_coef[tid][2 + l] = pk2(cquad, cquad);
        }
    } else if (tid >= 16 && tid < 16 + 48) {
        const int idx = tid - 16;
        const int l2 = idx & 1, j = (idx >> 1) & 1, l = (idx >> 2) & 1, r = idx >> 3;
        float acc = 0.0f;
        #pragma unroll
        for (int v = 0; v < NV; v++)
            acc += head_W[(r * NL + l) * NV + v] *
                   body_W[((r * NJ + j) * NV + v) * NL + l2];
        s_M[r * NJ + j][l * 2 + l2] = pk2(acc, acc);
    } else if (tid >= 64 && tid < 64 + NR * NL) {
        const int idx = tid - 64;
        const int r = idx >> 1, l = idx & 1;
        float acc = head_b[r * NL + l];
        #pragma unroll
        for (int v = 0; v < NV; v++)
            acc += head_W[(r * NL + l) * NV + v] *
                   (body_b[(r * NJ + 0) * NV + v] + body_b[(r * NJ + 1) * NV + v]);
        s_c[idx] = pk2(acc, acc);
    }
    __syncthreads();

    const int half = B >> 1;
    const int t = blockIdx.x * blockDim.x + tid;
    if (t >= half) return;

    // ---- load features of elements (t, t+half) into REGISTERS, packed ----
    u64 F0[NI], F1[NI];
    {
        const float4* fa = reinterpret_cast<const float4*>(feat + (size_t)t * (NI * NL));
        const float4* fb = reinterpret_cast<const float4*>(feat + (size_t)(t + half) * (NI * NL));
        #pragma unroll
        for (int k = 0; k < 6; k++) {
            const float4 a = fa[k];
            const float4 b = fb[k];
            F0[2 * k]     = pk2(a.x, b.x); F1[2 * k]     = pk2(a.y, b.y);
            F0[2 * k + 1] = pk2(a.z, b.z); F1[2 * k + 1] = pk2(a.w, b.w);
        }
    }

    // Single base offset; the second element's delta is launch-uniform.
    const size_t base  = (size_t)t * (NR * NL);
    const size_t delta = (size_t)half * (NR * NL);

    // ---- 12 sweeps, one (r,j) each; features stay in registers ----
    #pragma unroll 1
    for (int r = 0; r < NR; r++) {
        u64 A0 = s_c[2 * r + 0];
        u64 A1 = s_c[2 * r + 1];

        #pragma unroll 1
        for (int j = 0; j < NJ; j++) {
            const int rj = 2 * r + j;
            const u64 c0 = s_coef[rj][0], c1 = s_coef[rj][1];
            const u64 c2 = s_coef[rj][2], c3 = s_coef[rj][3];

            u64 se = 0ULL, n0 = 0ULL, n1 = 0ULL;
            #pragma unroll
            for (int i = 0; i < NI; i++) {
                const u64 t1 = fma2(c2, F0[i], c0);   // f0*(c0+c2*f0)
                const u64 t2 = fma2(c3, F1[i], c1);   // + f1*(c1+c3*f1)
                const u64 lg = fma2(F0[i], t1, mul2(F1[i], t2));
                float llo, lhi; upk2(lg, llo, lhi);
                const u64 e = pk2(ex2a(llo), ex2a(lhi));
                se = add2(se, e);
                n0 = fma2(e, F0[i], n0);
                n1 = fma2(e, F1[i], n1);
            }

            float slo, shi; upk2(se, slo, shi);
            const u64 rinv = pk2(rcpa(slo), rcpa(shi));
            const u64 s0 = mul2(n0, rinv);
            const u64 s1 = mul2(n1, rinv);

            A0 = fma2(s_M[rj][0], s0, fma2(s_M[rj][1], s1, A0));
            A1 = fma2(s_M[rj][2], s0, fma2(s_M[rj][3], s1, A1));
        }

        float x0, x1, y0, y1;
        upk2(A0, x0, x1);
        upk2(A1, y0, y1);
        *reinterpret_cast<float2*>(out + base + r * 2)         = make_float2(x0, y0);
        *reinterpret_cast<float2*>(out + base + delta + r * 2) = make_float2(x1, y1);
    }
}

extern "C" void kernel_launch(void* const* d_in, const int* in_sizes, int n_in,
                              void* d_out, int out_size) {
    const float* feat      = (const float*)d_in[0];
    const float* templates = (const float*)d_in[1];
    const float* gammas    = (const float*)d_in[2];
    const float* body_W    = (const float*)d_in[3];
    const float* body_b    = (const float*)d_in[4];
    const float* head_W    = (const float*)d_in[5];
    const float* head_b    = (const float*)d_in[6];
    float* out = (float*)d_out;

    const int B = in_sizes[0] / (NI * NL);
    const int half = B >> 1;
    const int blocks = (half + NT - 1) / NT;
    abstraction_layer_kernel<<<blocks, NT>>>(
        feat, templates, gammas, body_W, body_b, head_W, head_b, out, B);
}

// round 10
// speedup vs baseline: 1.0010x; 1.0010x over previous
#include <cuda_runtime.h>

// AbstractionLayer: B=524288, I=12, R=6, J=2, L=2, V=4
// Packed f32x2, 2 elements/thread (t, t+B/2). Features register-resident
// (24 packed u64 = 48 regs), zero inner-loop shared memory. R10: j-loop
// unrolled -> TWO independent (r,j) chains in flight per sweep (R5's ILP
// without R5's 36 LDS.128): 8 packed fma + 4 ex2 per i-iteration, epilogue
// of chain 0 overlaps accumulation of chain 1. ~94 regs, lb(128,5) leaves
// headroom (no forced cap -> no spills, the R7/R9 failure mode).
// Softmax max-pass removed (logits bounded); log2e folded into coefs (raw
// ex2.approx); head*body pre-fused; rcp.approx (tol 1e-3).

#define NI 12
#define NR 6
#define NJ 2
#define NL 2
#define NV 4
#define NRJ 12
#define NT 128
#define LOG2E 1.4426950408889634f

typedef unsigned long long u64;

__device__ __forceinline__ u64 pk2(float lo, float hi) {
    u64 r; asm("mov.b64 %0, {%1,%2};" : "=l"(r) : "f"(lo), "f"(hi)); return r;
}
__device__ __forceinline__ void upk2(u64 v, float& lo, float& hi) {
    asm("mov.b64 {%0,%1}, %2;" : "=f"(lo), "=f"(hi) : "l"(v));
}
__device__ __forceinline__ u64 fma2(u64 a, u64 b, u64 c) {
    u64 d; asm("fma.rn.f32x2 %0, %1, %2, %3;" : "=l"(d) : "l"(a), "l"(b), "l"(c)); return d;
}
__device__ __forceinline__ u64 mul2(u64 a, u64 b) {
    u64 d; asm("mul.rn.f32x2 %0, %1, %2;" : "=l"(d) : "l"(a), "l"(b)); return d;
}
__device__ __forceinline__ u64 add2(u64 a, u64 b) {
    u64 d; asm("add.rn.f32x2 %0, %1, %2;" : "=l"(d) : "l"(a), "l"(b)); return d;
}
__device__ __forceinline__ float ex2a(float x) {
    float r; asm("ex2.approx.ftz.f32 %0, %1;" : "=f"(r) : "f"(x)); return r;
}
__device__ __forceinline__ float rcpa(float x) {
    float r; asm("rcp.approx.ftz.f32 %0, %1;" : "=f"(r) : "f"(x)); return r;
}

__global__ __launch_bounds__(NT, 5)
void abstraction_layer_kernel(
    const float* __restrict__ feat,       // [B, I, L]
    const float* __restrict__ templates,  // [R, J, L]
    const float* __restrict__ gammas,     // [R, J, L]
    const float* __restrict__ body_W,     // [R, J, V, L]
    const float* __restrict__ body_b,     // [R, J, V]
    const float* __restrict__ head_W,     // [R, L, V]
    const float* __restrict__ head_b,     // [R, L]
    float* __restrict__ out,              // [B, R, L]
    int B)
{
    __shared__ u64 s_coef[NRJ][4];       // log2e-scaled logit coefs, lane-dup
    __shared__ u64 s_M[NRJ][4];          // fused head*body, lane-dup
    __shared__ u64 s_c[NR * NL];         // fused bias, lane-dup

    const int tid = threadIdx.x;

    // ---- one-time parameter fusion (disjoint thread ranges) ----
    if (tid < NRJ) {
        const int r = tid >> 1, j = tid & 1;
        #pragma unroll
        for (int l = 0; l < NL; l++) {
            float g = gammas[(r * NJ + j) * NL + l];
            g = fminf(fmaxf(g, 0.0f), 1.0f);
            const float w = 1.0f - g;
            const float t = templates[(r * NJ + j) * NL + l];
            const float clin  = 2.0f * w * t * LOG2E;
            const float cquad = -w * LOG2E;
            s_coef[tid][l]     = pk2(clin, clin);
            s_coef[tid][2 + l] = pk2(cquad, cquad);
        }
    } else if (tid >= 16 && tid < 16 + 48) {
        const int idx = tid - 16;
        const int l2 = idx & 1, j = (idx >> 1) & 1, l = (idx >> 2) & 1, r = idx >> 3;
        float acc = 0.0f;
        #pragma unroll
        for (int v = 0; v < NV; v++)
            acc += head_W[(r * NL + l) * NV + v] *
                   body_W[((r * NJ + j) * NV + v) * NL + l2];
        s_M[r * NJ + j][l * 2 + l2] = pk2(acc, acc);
    } else if (tid >= 64 && tid < 64 + NR * NL) {
        const int idx = tid - 64;
        const int r = idx >> 1, l = idx & 1;
        float acc = head_b[r * NL + l];
        #pragma unroll
        for (int v = 0; v < NV; v++)
            acc += head_W[(r * NL + l) * NV + v] *
                   (body_b[(r * NJ + 0) * NV + v] + body_b[(r * NJ + 1) * NV + v]);
        s_c[idx] = pk2(acc, acc);
    }
    __syncthreads();

    const int half = B >> 1;
    const int t = blockIdx.x * blockDim.x + tid;
    if (t >= half) return;

    // ---- load features of elements (t, t+half) into REGISTERS, packed ----
    u64 F0[NI], F1[NI];
    {
        const float4* fa = reinterpret_cast<const float4*>(feat + (size_t)t * (NI * NL));
        const float4* fb = reinterpret_cast<const float4*>(feat + (size_t)(t + half) * (NI * NL));
        #pragma unroll
        for (int k = 0; k < 6; k++) {
            const float4 a = fa[k];
            const float4 b = fb[k];
            F0[2 * k]     = pk2(a.x, b.x); F1[2 * k]     = pk2(a.y, b.y);
            F0[2 * k + 1] = pk2(a.z, b.z); F1[2 * k + 1] = pk2(a.w, b.w);
        }
    }

    const size_t base  = (size_t)t * (NR * NL);
    const size_t delta = (size_t)half * (NR * NL);

    // ---- 6 sweeps, TWO interleaved (r,j) chains each ----
    #pragma unroll 1
    for (int r = 0; r < NR; r++) {
        const int rj0 = 2 * r, rj1 = 2 * r + 1;

        const u64 c0a = s_coef[rj0][0], c1a = s_coef[rj0][1];
        const u64 c2a = s_coef[rj0][2], c3a = s_coef[rj0][3];
        const u64 c0b = s_coef[rj1][0], c1b = s_coef[rj1][1];
        const u64 c2b = s_coef[rj1][2], c3b = s_coef[rj1][3];

        u64 sea = 0ULL, n0a = 0ULL, n1a = 0ULL;
        u64 seb = 0ULL, n0b = 0ULL, n1b = 0ULL;

        #pragma unroll
        for (int i = 0; i < NI; i++) {
            const u64 f0 = F0[i], f1 = F1[i];
            // chain A logit
            const u64 ta1 = fma2(c2a, f0, c0a);
            const u64 ta2 = fma2(c3a, f1, c1a);
            const u64 lga = fma2(f0, ta1, mul2(f1, ta2));
            // chain B logit
            const u64 tb1 = fma2(c2b, f0, c0b);
            const u64 tb2 = fma2(c3b, f1, c1b);
            const u64 lgb = fma2(f0, tb1, mul2(f1, tb2));

            float la0, la1, lb0, lb1;
            upk2(lga, la0, la1);
            upk2(lgb, lb0, lb1);
            const u64 ea = pk2(ex2a(la0), ex2a(la1));
            const u64 eb = pk2(ex2a(lb0), ex2a(lb1));

            sea = add2(sea, ea);
            n0a = fma2(ea, f0, n0a);
            n1a = fma2(ea, f1, n1a);
            seb = add2(seb, eb);
            n0b = fma2(eb, f0, n0b);
            n1b = fma2(eb, f1, n1b);
        }

        // epilogue: both chains -> rule r outputs
        u64 A0 = s_c[2 * r + 0];
        u64 A1 = s_c[2 * r + 1];

        float sa0, sa1, sb0, sb1;
        upk2(sea, sa0, sa1);
        upk2(seb, sb0, sb1);
        const u64 ra = pk2(rcpa(sa0), rcpa(sa1));
        const u64 rb = pk2(rcpa(sb0), rcpa(sb1));

        const u64 s0a = mul2(n0a, ra), s1a = mul2(n1a, ra);
        const u64 s0b = mul2(n0b, rb), s1b = mul2(n1b, rb);

        A0 = fma2(s_M[rj0][0], s0a, fma2(s_M[rj0][1], s1a, A0));
        A1 = fma2(s_M[rj0][2], s0a, fma2(s_M[rj0][3], s1a, A1));
        A0 = fma2(s_M[rj1][0], s0b, fma2(s_M[rj1][1], s1b, A0));
        A1 = fma2(s_M[rj1][2], s0b, fma2(s_M[rj1][3], s1b, A1));

        float x0, x1, y0, y1;
        upk2(A0, x0, x1);
        upk2(A1, y0, y1);
        *reinterpret_cast<float2*>(out + base + r * 2)         = make_float2(x0, y0);
        *reinterpret_cast<float2*>(out + base + delta + r * 2) = make_float2(x1, y1);
    }
}

extern "C" void kernel_launch(void* const* d_in, const int* in_sizes, int n_in,
                              void* d_out, int out_size) {
    const float* feat      = (const float*)d_in[0];
    const float* templates = (const float*)d_in[1];
    const float* gammas    = (const float*)d_in[2];
    const float* body_W    = (const float*)d_in[3];
    const float* body_b    = (const float*)d_in[4];
    const float* head_W    = (const float*)d_in[5];
    const float* head_b    = (const float*)d_in[6];
    float* out = (float*)d_out;

    const int B = in_sizes[0] / (NI * NL);
    const int half = B >> 1;
    const int blocks = (half + NT - 1) / NT;
    abstraction_layer_kernel<<<blocks, NT>>>(
        feat, templates, gammas, body_W, body_b, head_W, head_b, out, B);
}